// round 4
// baseline (speedup 1.0000x reference)
#include <cuda_runtime.h>

#define CDIV(a,b) (((a)+(b)-1)/(b))

#define NN 100000
#define NE 1600000

typedef unsigned long long ull;

// ---------------- device scratch (static; no cudaMalloc) ----------------
__device__ int   g_deg[NN];
__device__ int   g_off[NN + 1];
__device__ int   g_cur[NN];
__device__ int   g_csr[NE];
__device__ float g_agg[(size_t)NN * 64];
__device__ float g_h0 [(size_t)NN * 64];
__device__ float g_h1 [(size_t)NN * 64];

__device__ __forceinline__ const float* sel_buf(int s, const float* ext) {
    return s == 0 ? ext : (s == 1 ? g_h0 : g_h1);
}

// packed f32x2 FMA: d = a*b + d (elementwise on 2 packed floats)
__device__ __forceinline__ void fma2(ull& d, ull a, ull b) {
    asm("fma.rn.f32x2 %0, %1, %2, %0;" : "+l"(d) : "l"(a), "l"(b));
}

union U64F2 { ull u; float2 f; };

// ---------------- CSR construction ----------------
__global__ void k_zero_deg() {
    int i = blockIdx.x * blockDim.x + threadIdx.x;
    if (i < NN) g_deg[i] = 0;
}

// 4 edges per thread, int4 loads (NE divisible by 4)
__global__ void k_count(const int* __restrict__ ei) {
    int e4 = blockIdx.x * blockDim.x + threadIdx.x;
    if (e4 < NE / 4) {
        int4 d = ((const int4*)(ei + NE))[e4];
        atomicAdd(&g_deg[d.x], 1);
        atomicAdd(&g_deg[d.y], 1);
        atomicAdd(&g_deg[d.z], 1);
        atomicAdd(&g_deg[d.w], 1);
    }
}

// single-block exclusive scan over 100k degrees
__global__ void k_scan() {
    __shared__ int sums[1024];
    const int CH = 98;  // 1024*98 >= NN
    int t = threadIdx.x;
    int b = t * CH;
    int e = min(b + CH, NN);
    int s = 0;
    for (int i = b; i < e; i++) s += g_deg[i];
    sums[t] = s;
    __syncthreads();
    for (int o = 1; o < 1024; o <<= 1) {
        int v = (t >= o) ? sums[t - o] : 0;
        __syncthreads();
        sums[t] += v;
        __syncthreads();
    }
    int run = (t == 0) ? 0 : sums[t - 1];
    for (int i = b; i < e; i++) {
        g_off[i] = run;
        g_cur[i] = run;
        run += g_deg[i];
    }
    if (t == 1023) g_off[NN] = run;
}

__global__ void k_scatter(const int* __restrict__ ei) {
    int e4 = blockIdx.x * blockDim.x + threadIdx.x;
    if (e4 < NE / 4) {
        int4 s = ((const int4*)ei)[e4];
        int4 d = ((const int4*)(ei + NE))[e4];
        g_csr[atomicAdd(&g_cur[d.x], 1)] = s.x;
        g_csr[atomicAdd(&g_cur[d.y], 1)] = s.y;
        g_csr[atomicAdd(&g_cur[d.z], 1)] = s.z;
        g_csr[atomicAdd(&g_cur[d.w], 1)] = s.w;
    }
}

// ---------------- mean aggregation: warp per destination node ----------------
__global__ void k_agg(const float* __restrict__ xext, int xsel) {
    int gw   = (blockIdx.x * blockDim.x + threadIdx.x) >> 5;
    int lane = threadIdx.x & 31;
    if (gw >= NN) return;
    const float* __restrict__ x = sel_buf(xsel, xext);
    int beg = g_off[gw];
    int end = g_off[gw + 1];
    const float2* __restrict__ x2 = (const float2*)x;
    float sx = 0.f, sy = 0.f;
    int e = beg;
    #pragma unroll 1
    for (; e + 4 <= end; e += 4) {
        int s0 = g_csr[e + 0];
        int s1 = g_csr[e + 1];
        int s2 = g_csr[e + 2];
        int s3 = g_csr[e + 3];
        float2 v0 = x2[(size_t)s0 * 32 + lane];
        float2 v1 = x2[(size_t)s1 * 32 + lane];
        float2 v2 = x2[(size_t)s2 * 32 + lane];
        float2 v3 = x2[(size_t)s3 * 32 + lane];
        sx += v0.x + v1.x + v2.x + v3.x;
        sy += v0.y + v1.y + v2.y + v3.y;
    }
    for (; e < end; ++e) {
        int s = g_csr[e];
        float2 v = x2[(size_t)s * 32 + lane];
        sx += v.x;
        sy += v.y;
    }
    int d = end - beg;
    float inv = d > 0 ? 1.f / (float)d : 0.f;
    float2 o;
    o.x = sx * inv;
    o.y = sy * inv;
    ((float2*)g_agg)[(size_t)gw * 32 + lane] = o;
}

// ---------------- fused GEMM with packed f32x2 FMA ----------------
// out = [agg | A1] @ [B0;B1] + bias (, ReLU). M=100000, K=KTOT, N=NOUT.
// Block tile 128 x NOUT, 128 threads, per-thread 8m x CN n.
// Accumulators packed across m: acc2[4][CN] f32x2; a-pairs load 64-bit from As
// (contiguous m); B staged DUPLICATED in smem so b-broadcast pairs are one LDS.64.
template <int KTOT, int NOUT, bool RELU, bool SPLIT>
__global__ void __launch_bounds__(128)
k_gemm(const float* __restrict__ xext, int asel, int dsel,
       const float* __restrict__ B0, const float* __restrict__ B1,
       const float* __restrict__ bias, float* __restrict__ oext) {
    constexpr int BM  = 128;
    constexpr int LDA = 132;
    constexpr int CN  = NOUT / 8;
    __shared__ float As[32][LDA];
    __shared__ float Bs[32][2 * NOUT];   // duplicated pairs

    const float* __restrict__ A1 = sel_buf(asel, xext);
    const float* __restrict__ A0 = SPLIT ? (const float*)g_agg : A1;
    float* __restrict__ out = (dsel == 0) ? oext : (dsel == 1 ? g_h0 : g_h1);

    const int t     = threadIdx.x;
    const int mbase = blockIdx.x * BM;
    const int m0    = (t & 15) * 8;
    const int n0    = (t >> 4) * CN;

    ull acc2[4][CN];
    #pragma unroll
    for (int i = 0; i < 4; i++)
        #pragma unroll
        for (int j = 0; j < CN; j++) acc2[i][j] = 0ull;

    #pragma unroll 1
    for (int kt = 0; kt < KTOT; kt += 32) {
        // stage A tile transposed: lane=k, rows coalesced
        {
            const int kl = t & 31;
            const int k  = kt + kl;
            const float* __restrict__ Asrc = (SPLIT && k >= 64) ? A1 : A0;
            const int kk = (SPLIT && k >= 64) ? (k - 64) : k;
            #pragma unroll
            for (int mm = (t >> 5); mm < BM; mm += 4) {
                int row = mbase + mm;
                As[kl][mm] = (row < NN) ? Asrc[(size_t)row * 64 + kk] : 0.f;
            }
        }
        // stage B tile duplicated: Bs[k][2c]=Bs[k][2c+1]=B[k][c]
        #pragma unroll
        for (int idx = t; idx < 32 * NOUT; idx += 128) {
            int kk = idx / NOUT;
            int c  = idx % NOUT;
            int k  = kt + kk;
            float w = (SPLIT && k >= 64) ? B1[(size_t)(k - 64) * NOUT + c]
                                         : B0[(size_t)k * NOUT + c];
            float2 wd = make_float2(w, w);
            *(float2*)&Bs[kk][2 * c] = wd;
        }
        __syncthreads();

        #pragma unroll
        for (int k = 0; k < 32; k++) {
            ull a2[4];
            #pragma unroll
            for (int ip = 0; ip < 4; ip++)
                a2[ip] = *(const ull*)&As[k][m0 + 2 * ip];
            ull b2[CN];
            #pragma unroll
            for (int j = 0; j < CN; j++)
                b2[j] = *(const ull*)&Bs[k][2 * (n0 + j)];
            #pragma unroll
            for (int ip = 0; ip < 4; ip++)
                #pragma unroll
                for (int j = 0; j < CN; j++)
                    fma2(acc2[ip][j], a2[ip], b2[j]);
        }
        __syncthreads();
    }

    // epilogue: bias (+ReLU), vectorized stores
    float bv[CN];
    #pragma unroll
    for (int j = 0; j < CN; j++) bv[j] = bias[n0 + j];

    #pragma unroll
    for (int ip = 0; ip < 4; ip++) {
        #pragma unroll
        for (int h = 0; h < 2; h++) {
            int row = mbase + m0 + 2 * ip + h;
            if (row < NN) {
                float v[CN];
                #pragma unroll
                for (int j = 0; j < CN; j++) {
                    U64F2 u; u.u = acc2[ip][j];
                    float r = (h ? u.f.y : u.f.x) + bv[j];
                    if (RELU) r = fmaxf(r, 0.f);
                    v[j] = r;
                }
                float* op = &out[(size_t)row * NOUT + n0];
                if constexpr (CN == 8) {
                    *(float4*)(op)     = make_float4(v[0], v[1], v[2], v[3]);
                    *(float4*)(op + 4) = make_float4(v[4], v[5], v[6], v[7]);
                } else {
                    *(float4*)(op) = make_float4(v[0], v[1], v[2], v[3]);
                }
            }
        }
    }
}

// ---------------- host launcher (pure kernel launches; graph-capturable) ----------------
extern "C" void kernel_launch(void* const* d_in, const int* in_sizes, int n_in,
                              void* d_out, int out_size) {
    const float* x    = (const float*)d_in[0];
    const int*   ei   = (const int*)d_in[1];     // int32 edge_index (2, NE)
    const float* Wl1  = (const float*)d_in[2];
    const float* Wr1  = (const float*)d_in[3];
    const float* b1   = (const float*)d_in[4];
    const float* Wl2  = (const float*)d_in[5];
    const float* Wr2  = (const float*)d_in[6];
    const float* b2   = (const float*)d_in[7];
    const float* Wl3  = (const float*)d_in[8];
    const float* Wr3  = (const float*)d_in[9];
    const float* b3   = (const float*)d_in[10];
    const float* Wlin = (const float*)d_in[11];
    const float* blin = (const float*)d_in[12];
    float*       out  = (float*)d_out;

    // CSR build (per launch; deterministic)
    k_zero_deg<<<CDIV(NN, 256), 256>>>();
    k_count<<<CDIV(NE / 4, 256), 256>>>(ei);
    k_scan<<<1, 1024>>>();
    k_scatter<<<CDIV(NE / 4, 256), 256>>>(ei);

    const int AGG_BLOCKS  = CDIV(NN, 8);        // 8 warps/block, warp/node
    const int GEMM_BLOCKS = CDIV(NN, 128);

    // layer 1: agg(x) -> h0 = relu([agg|x]@[Wl1;Wr1]+b1)
    k_agg<<<AGG_BLOCKS, 256>>>(x, 0);
    k_gemm<128, 64, true, true><<<GEMM_BLOCKS, 128>>>(x, 0, 1, Wl1, Wr1, b1, nullptr);
    // layer 2: agg(h0) -> h1
    k_agg<<<AGG_BLOCKS, 256>>>(nullptr, 1);
    k_gemm<128, 64, true, true><<<GEMM_BLOCKS, 128>>>(nullptr, 1, 2, Wl2, Wr2, b2, nullptr);
    // layer 3: agg(h1) -> h0
    k_agg<<<AGG_BLOCKS, 256>>>(nullptr, 2);
    k_gemm<128, 64, true, true><<<GEMM_BLOCKS, 128>>>(nullptr, 2, 1, Wl3, Wr3, b3, nullptr);
    // final linear: out = h0 @ Wlin + blin
    k_gemm<64, 32, false, false><<<GEMM_BLOCKS, 128>>>(nullptr, 1, 0, Wlin, nullptr, blin, out);
}

// round 5
// speedup vs baseline: 1.1466x; 1.1466x over previous
#include <cuda_runtime.h>
#include <cstdint>

#define CDIV(a,b) (((a)+(b)-1)/(b))

#define NN 100000
#define NE 1600000

// ---------------- device scratch (static; no cudaMalloc) ----------------
__device__ int   g_deg[NN];
__device__ int   g_off[NN + 1];
__device__ int   g_cur[NN];
__device__ int   g_csr[NE];
__device__ float g_agg[(size_t)NN * 64];
__device__ float g_h0 [(size_t)NN * 64];
__device__ float g_h1 [(size_t)NN * 64];

__device__ __forceinline__ const float* sel_buf(int s, const float* ext) {
    return s == 0 ? ext : (s == 1 ? g_h0 : g_h1);
}

// ---------------- tf32 helpers ----------------
__device__ __forceinline__ uint32_t f2tf32(float f) {
    uint32_t r;
    asm("cvt.rna.tf32.f32 %0, %1;" : "=r"(r) : "f"(f));
    return r;
}
__device__ __forceinline__ void split_tf32(float f, uint32_t& hi, uint32_t& lo) {
    hi = f2tf32(f);
    float rem = f - __uint_as_float(hi);
    lo = f2tf32(rem);
}
__device__ __forceinline__ void mma_tf32(float* c, const uint32_t* a, uint32_t b0, uint32_t b1) {
    asm volatile(
        "mma.sync.aligned.m16n8k8.row.col.f32.tf32.tf32.f32 "
        "{%0,%1,%2,%3}, {%4,%5,%6,%7}, {%8,%9}, {%0,%1,%2,%3};"
        : "+f"(c[0]), "+f"(c[1]), "+f"(c[2]), "+f"(c[3])
        : "r"(a[0]), "r"(a[1]), "r"(a[2]), "r"(a[3]), "r"(b0), "r"(b1));
}

// ---------------- CSR construction (scalar versions; R3-proven) ----------------
__global__ void k_zero_deg() {
    int i = blockIdx.x * blockDim.x + threadIdx.x;
    if (i < NN) g_deg[i] = 0;
}

__global__ void k_count(const int* __restrict__ ei) {
    int e = blockIdx.x * blockDim.x + threadIdx.x;
    if (e < NE) {
        int dst = ei[NE + e];
        atomicAdd(&g_deg[dst], 1);
    }
}

__global__ void k_scan() {
    __shared__ int sums[1024];
    const int CH = 98;
    int t = threadIdx.x;
    int b = t * CH;
    int e = min(b + CH, NN);
    int s = 0;
    for (int i = b; i < e; i++) s += g_deg[i];
    sums[t] = s;
    __syncthreads();
    for (int o = 1; o < 1024; o <<= 1) {
        int v = (t >= o) ? sums[t - o] : 0;
        __syncthreads();
        sums[t] += v;
        __syncthreads();
    }
    int run = (t == 0) ? 0 : sums[t - 1];
    for (int i = b; i < e; i++) {
        g_off[i] = run;
        g_cur[i] = run;
        run += g_deg[i];
    }
    if (t == 1023) g_off[NN] = run;
}

__global__ void k_scatter(const int* __restrict__ ei) {
    int e = blockIdx.x * blockDim.x + threadIdx.x;
    if (e < NE) {
        int src = ei[e];
        int dst = ei[NE + e];
        int p = atomicAdd(&g_cur[dst], 1);
        g_csr[p] = src;
    }
}

// ---------------- mean aggregation: warp per destination node ----------------
__global__ void k_agg(const float* __restrict__ xext, int xsel) {
    int gw   = (blockIdx.x * blockDim.x + threadIdx.x) >> 5;
    int lane = threadIdx.x & 31;
    if (gw >= NN) return;
    const float* __restrict__ x = sel_buf(xsel, xext);
    int beg = g_off[gw];
    int end = g_off[gw + 1];
    const float2* __restrict__ x2 = (const float2*)x;
    float sx = 0.f, sy = 0.f;
    int e = beg;
    #pragma unroll 1
    for (; e + 4 <= end; e += 4) {
        int s0 = g_csr[e + 0];
        int s1 = g_csr[e + 1];
        int s2 = g_csr[e + 2];
        int s3 = g_csr[e + 3];
        float2 v0 = x2[(size_t)s0 * 32 + lane];
        float2 v1 = x2[(size_t)s1 * 32 + lane];
        float2 v2 = x2[(size_t)s2 * 32 + lane];
        float2 v3 = x2[(size_t)s3 * 32 + lane];
        sx += v0.x + v1.x + v2.x + v3.x;
        sy += v0.y + v1.y + v2.y + v3.y;
    }
    for (; e < end; ++e) {
        int s = g_csr[e];
        float2 v = x2[(size_t)s * 32 + lane];
        sx += v.x;
        sy += v.y;
    }
    int d = end - beg;
    float inv = d > 0 ? 1.f / (float)d : 0.f;
    float2 o;
    o.x = sx * inv;
    o.y = sy * inv;
    ((float2*)g_agg)[(size_t)gw * 32 + lane] = o;
}

// ---------------- tensor-core GEMM (3xTF32): out = [agg|A1]@[B0;B1] + bias (,ReLU) ----
// M=100000, K=KTOT (128 layers / 64 final), N=NOUT (64 / 32).
// Block: 256 threads = 8 warps; tile 128(m) x NOUT(n); BK=32 per stage.
// Warp w owns rows [w*16, w*16+16); does NOUT/8 n-tiles of m16n8k8 per k-step.
// A staged fp32 transposed As[k][m] (LDA=136: conflict-free frag loads);
// B staged pre-split hi/lo (LDB=NOUT+8: conflict-free).
template <int KTOT, int NOUT, bool RELU, bool SPLIT>
__global__ void __launch_bounds__(256)
k_gemm(const float* __restrict__ xext, int asel, int dsel,
       const float* __restrict__ B0, const float* __restrict__ B1,
       const float* __restrict__ bias, float* __restrict__ oext) {
    constexpr int BM  = 128;
    constexpr int LDA = 136;
    constexpr int LDB = NOUT + 8;
    constexpr int NT  = NOUT / 8;
    __shared__ float As[32][LDA];
    __shared__ float Bh[32][LDB];
    __shared__ float Bl[32][LDB];

    const float* __restrict__ A1 = sel_buf(asel, xext);
    const float* __restrict__ A0 = SPLIT ? (const float*)g_agg : A1;
    float* __restrict__ out = (dsel == 0) ? oext : (dsel == 1 ? g_h0 : g_h1);

    const int t     = threadIdx.x;
    const int lane  = t & 31;
    const int wid   = t >> 5;          // 0..7
    const int g     = lane >> 2;       // 0..7
    const int tg    = lane & 3;        // 0..3
    const int mbase = blockIdx.x * BM;
    const int wm    = wid * 16;
    const int ma    = wm + g;

    float c[NT][4];
    #pragma unroll
    for (int nt = 0; nt < NT; nt++)
        #pragma unroll
        for (int i = 0; i < 4; i++) c[nt][i] = 0.f;

    #pragma unroll 1
    for (int kt = 0; kt < KTOT; kt += 32) {
        // stage A (transposed): lane = k within tile, warp reads one row/iter (coalesced)
        {
            const int kl = lane;
            const int k  = kt + kl;
            const float* __restrict__ Asrc = (SPLIT && k >= 64) ? A1 : A0;
            const int kk = (SPLIT && k >= 64) ? (k - 64) : k;
            #pragma unroll
            for (int mm = wid; mm < BM; mm += 8) {
                int row = mbase + mm;
                As[kl][mm] = (row < NN) ? Asrc[(size_t)row * 64 + kk] : 0.f;
            }
        }
        // stage B pre-split hi/lo
        #pragma unroll
        for (int idx = t; idx < 32 * NOUT; idx += 256) {
            int kk = idx / NOUT;
            int cc = idx % NOUT;
            int k  = kt + kk;
            float w = (SPLIT && k >= 64) ? B1[(size_t)(k - 64) * NOUT + cc]
                                         : B0[(size_t)k * NOUT + cc];
            uint32_t hi, lo;
            split_tf32(w, hi, lo);
            Bh[kk][cc] = __uint_as_float(hi);
            Bl[kk][cc] = __uint_as_float(lo);
        }
        __syncthreads();

        #pragma unroll
        for (int ks = 0; ks < 4; ks++) {
            const int k0 = ks * 8 + tg;
            float a0f = As[k0][ma];
            float a1f = As[k0][ma + 8];
            float a2f = As[k0 + 4][ma];
            float a3f = As[k0 + 4][ma + 8];
            uint32_t ah[4], al[4];
            split_tf32(a0f, ah[0], al[0]);
            split_tf32(a1f, ah[1], al[1]);
            split_tf32(a2f, ah[2], al[2]);
            split_tf32(a3f, ah[3], al[3]);
            #pragma unroll
            for (int nt = 0; nt < NT; nt++) {
                uint32_t bh0 = __float_as_uint(Bh[k0][nt * 8 + g]);
                uint32_t bh1 = __float_as_uint(Bh[k0 + 4][nt * 8 + g]);
                uint32_t bl0 = __float_as_uint(Bl[k0][nt * 8 + g]);
                uint32_t bl1 = __float_as_uint(Bl[k0 + 4][nt * 8 + g]);
                mma_tf32(c[nt], al, bh0, bh1);   // small terms first
                mma_tf32(c[nt], ah, bl0, bl1);
                mma_tf32(c[nt], ah, bh0, bh1);
            }
        }
        __syncthreads();
    }

    // epilogue: bias (+ReLU), float2 stores (cols 2tg,2tg+1 contiguous)
    const int r0 = mbase + wm + g;
    const int r1 = r0 + 8;
    #pragma unroll
    for (int nt = 0; nt < NT; nt++) {
        const int col = nt * 8 + 2 * tg;
        float bx = bias[col];
        float by = bias[col + 1];
        if (r0 < NN) {
            float vx = c[nt][0] + bx;
            float vy = c[nt][1] + by;
            if (RELU) { vx = fmaxf(vx, 0.f); vy = fmaxf(vy, 0.f); }
            *(float2*)&out[(size_t)r0 * NOUT + col] = make_float2(vx, vy);
        }
        if (r1 < NN) {
            float vx = c[nt][2] + bx;
            float vy = c[nt][3] + by;
            if (RELU) { vx = fmaxf(vx, 0.f); vy = fmaxf(vy, 0.f); }
            *(float2*)&out[(size_t)r1 * NOUT + col] = make_float2(vx, vy);
        }
    }
}

// ---------------- host launcher (pure kernel launches; graph-capturable) ----------------
extern "C" void kernel_launch(void* const* d_in, const int* in_sizes, int n_in,
                              void* d_out, int out_size) {
    const float* x    = (const float*)d_in[0];
    const int*   ei   = (const int*)d_in[1];
    const float* Wl1  = (const float*)d_in[2];
    const float* Wr1  = (const float*)d_in[3];
    const float* b1   = (const float*)d_in[4];
    const float* Wl2  = (const float*)d_in[5];
    const float* Wr2  = (const float*)d_in[6];
    const float* b2   = (const float*)d_in[7];
    const float* Wl3  = (const float*)d_in[8];
    const float* Wr3  = (const float*)d_in[9];
    const float* b3   = (const float*)d_in[10];
    const float* Wlin = (const float*)d_in[11];
    const float* blin = (const float*)d_in[12];
    float*       out  = (float*)d_out;

    // CSR build
    k_zero_deg<<<CDIV(NN, 256), 256>>>();
    k_count<<<CDIV(NE, 256), 256>>>(ei);
    k_scan<<<1, 1024>>>();
    k_scatter<<<CDIV(NE, 256), 256>>>(ei);

    const int AGG_BLOCKS  = CDIV(NN, 8);
    const int GEMM_BLOCKS = CDIV(NN, 128);

    // layer 1
    k_agg<<<AGG_BLOCKS, 256>>>(x, 0);
    k_gemm<128, 64, true, true><<<GEMM_BLOCKS, 256>>>(x, 0, 1, Wl1, Wr1, b1, nullptr);
    // layer 2
    k_agg<<<AGG_BLOCKS, 256>>>(nullptr, 1);
    k_gemm<128, 64, true, true><<<GEMM_BLOCKS, 256>>>(nullptr, 1, 2, Wl2, Wr2, b2, nullptr);
    // layer 3
    k_agg<<<AGG_BLOCKS, 256>>>(nullptr, 2);
    k_gemm<128, 64, true, true><<<GEMM_BLOCKS, 256>>>(nullptr, 2, 1, Wl3, Wr3, b3, nullptr);
    // final linear
    k_gemm<64, 32, false, false><<<GEMM_BLOCKS, 256>>>(nullptr, 1, 0, Wlin, nullptr, blin, out);
}

// round 6
// speedup vs baseline: 2.1772x; 1.8989x over previous
#include <cuda_runtime.h>
#include <cstdint>

#define CDIV(a,b) (((a)+(b)-1)/(b))

#define NN 100000
#define NE 1600000
#define SCAN_BS 512
#define NPART ((NN + SCAN_BS - 1) / SCAN_BS)   // 196

// ---------------- device scratch (static; no cudaMalloc) ----------------
__device__ int   g_deg[NN];
__device__ int   g_off[NN + 1];
__device__ int   g_cur[NN];
__device__ int   g_csr[NE];
__device__ int   g_part[256];
__device__ float g_agg[(size_t)NN * 64];
__device__ float g_h0 [(size_t)NN * 64];
__device__ float g_h1 [(size_t)NN * 64];

__device__ __forceinline__ const float* sel_buf(int s, const float* ext) {
    return s == 0 ? ext : (s == 1 ? g_h0 : g_h1);
}

// ---------------- bf16 split helpers ----------------
// hi = truncate-to-bf16(f) (exact bf16), lo = f - hi (exact)
__device__ __forceinline__ void bsplit(float f, uint32_t& hu, float& lo) {
    hu = __float_as_uint(f) & 0xFFFF0000u;
    lo = f - __uint_as_float(hu);
}
__device__ __forceinline__ uint32_t cvt_bf16x2(float hi_elem, float lo_elem) {
    uint32_t r;
    asm("cvt.rn.bf16x2.f32 %0, %1, %2;" : "=r"(r) : "f"(hi_elem), "f"(lo_elem));
    return r;
}
// pack two floats (f0 -> low half = even k, f1 -> high half = odd k) into hi/lo bf16x2
__device__ __forceinline__ void split_pack2(float f0, float f1, uint32_t& hp, uint32_t& lp) {
    uint32_t h0, h1;
    float l0, l1;
    bsplit(f0, h0, l0);
    bsplit(f1, h1, l1);
    hp = (h0 >> 16) | h1;            // exact bf16 bit-pack
    lp = cvt_bf16x2(l1, l0);         // rounded residuals
}

__device__ __forceinline__ void mma_bf16(float* c, const uint32_t* a, uint32_t b0, uint32_t b1) {
    asm volatile(
        "mma.sync.aligned.m16n8k16.row.col.f32.bf16.bf16.f32 "
        "{%0,%1,%2,%3}, {%4,%5,%6,%7}, {%8,%9}, {%0,%1,%2,%3};"
        : "+f"(c[0]), "+f"(c[1]), "+f"(c[2]), "+f"(c[3])
        : "r"(a[0]), "r"(a[1]), "r"(a[2]), "r"(a[3]), "r"(b0), "r"(b1));
}

// ---------------- CSR construction ----------------
__global__ void k_zero_deg() {
    int i = blockIdx.x * blockDim.x + threadIdx.x;
    if (i < NN) g_deg[i] = 0;
}

__global__ void k_count(const int* __restrict__ ei) {
    int e = blockIdx.x * blockDim.x + threadIdx.x;
    if (e < NE) atomicAdd(&g_deg[ei[NE + e]], 1);
}

// phase 1: per-block sums of degrees
__global__ void __launch_bounds__(SCAN_BS) k_blocksum() {
    __shared__ int ws[16];
    int i = blockIdx.x * SCAN_BS + threadIdx.x;
    int v = (i < NN) ? g_deg[i] : 0;
    #pragma unroll
    for (int o = 16; o > 0; o >>= 1) v += __shfl_down_sync(0xFFFFFFFFu, v, o);
    int lane = threadIdx.x & 31, wid = threadIdx.x >> 5;
    if (lane == 0) ws[wid] = v;
    __syncthreads();
    if (wid == 0) {
        int s = (lane < 16) ? ws[lane] : 0;
        #pragma unroll
        for (int o = 8; o > 0; o >>= 1) s += __shfl_down_sync(0xFFFFFFFFu, s, o);
        if (lane == 0) g_part[blockIdx.x] = s;
    }
}

// phase 2: exclusive scan of NPART block sums (single small block)
__global__ void k_scanpart() {
    __shared__ int sm[256];
    int t = threadIdx.x;
    int v = (t < NPART) ? g_part[t] : 0;
    sm[t] = v;
    __syncthreads();
    #pragma unroll
    for (int o = 1; o < 256; o <<= 1) {
        int u = (t >= o) ? sm[t - o] : 0;
        __syncthreads();
        sm[t] += u;
        __syncthreads();
    }
    if (t < NPART) g_part[t] = sm[t] - v;  // exclusive
}

// phase 3: per-block exclusive scan + base -> offsets
__global__ void __launch_bounds__(SCAN_BS) k_offsets() {
    __shared__ int ws[16];
    int i = blockIdx.x * SCAN_BS + threadIdx.x;
    int lane = threadIdx.x & 31, wid = threadIdx.x >> 5;
    int v = (i < NN) ? g_deg[i] : 0;
    int incl = v;
    #pragma unroll
    for (int o = 1; o < 32; o <<= 1) {
        int u = __shfl_up_sync(0xFFFFFFFFu, incl, o);
        if (lane >= o) incl += u;
    }
    if (lane == 31) ws[wid] = incl;
    __syncthreads();
    if (wid == 0) {
        int s = (lane < 16) ? ws[lane] : 0;
        int si = s;
        #pragma unroll
        for (int o = 1; o < 32; o <<= 1) {
            int u = __shfl_up_sync(0xFFFFFFFFu, si, o);
            if (lane >= o) si += u;
        }
        if (lane < 16) ws[lane] = si - s;  // exclusive warp bases
    }
    __syncthreads();
    if (i < NN) {
        int off = g_part[blockIdx.x] + ws[wid] + incl - v;
        g_off[i] = off;
        g_cur[i] = off;
    }
    if (blockIdx.x == 0 && threadIdx.x == 0) g_off[NN] = NE;
}

__global__ void k_scatter(const int* __restrict__ ei) {
    int e = blockIdx.x * blockDim.x + threadIdx.x;
    if (e < NE) {
        int src = ei[e];
        int dst = ei[NE + e];
        g_csr[atomicAdd(&g_cur[dst], 1)] = src;
    }
}

// ---------------- mean aggregation: warp per node, half-warp per edge ----------------
// lanes 0..15 handle even edges, 16..31 odd edges; each lane reads float4 (4 ch).
__global__ void k_agg(const float* __restrict__ xext, int xsel) {
    int gw   = (blockIdx.x * blockDim.x + threadIdx.x) >> 5;
    int lane = threadIdx.x & 31;
    if (gw >= NN) return;
    const float* __restrict__ x = sel_buf(xsel, xext);
    const float4* __restrict__ x4 = (const float4*)x;
    int beg = g_off[gw];
    int end = g_off[gw + 1];
    int half = lane >> 4;        // 0 or 1
    int li   = lane & 15;        // channel group: 4*li .. 4*li+3
    float4 acc = make_float4(0.f, 0.f, 0.f, 0.f);
    int e = beg + half;
    // unroll-2: up to 4 edges in flight across the warp
    #pragma unroll 1
    for (; e + 2 < end; e += 4) {
        int s0 = g_csr[e];
        int s1 = g_csr[e + 2];
        float4 v0 = x4[(size_t)s0 * 16 + li];
        float4 v1 = x4[(size_t)s1 * 16 + li];
        acc.x += v0.x + v1.x;
        acc.y += v0.y + v1.y;
        acc.z += v0.z + v1.z;
        acc.w += v0.w + v1.w;
    }
    if (e < end) {
        int s = g_csr[e];
        float4 v = x4[(size_t)s * 16 + li];
        acc.x += v.x; acc.y += v.y; acc.z += v.z; acc.w += v.w;
    }
    // merge odd/even halves: lane <-> lane^16
    acc.x += __shfl_xor_sync(0xFFFFFFFFu, acc.x, 16);
    acc.y += __shfl_xor_sync(0xFFFFFFFFu, acc.y, 16);
    acc.z += __shfl_xor_sync(0xFFFFFFFFu, acc.z, 16);
    acc.w += __shfl_xor_sync(0xFFFFFFFFu, acc.w, 16);
    if (half == 0) {
        int d = end - beg;
        float inv = d > 0 ? 1.f / (float)d : 0.f;
        acc.x *= inv; acc.y *= inv; acc.z *= inv; acc.w *= inv;
        ((float4*)g_agg)[(size_t)gw * 16 + li] = acc;
    }
}

// ---------------- bf16 3-term split tensor GEMM ----------------
// out = [agg | A1] @ [B0;B1] + bias (,ReLU). Block: 256 thr = 8 warps, tile 128 x NOUT.
// Stage BK=32 (16 packed k2 rows); A and B pre-split hi/lo packed bf16x2 in smem.
template <int KTOT, int NOUT, bool RELU, bool SPLIT>
__global__ void __launch_bounds__(256)
k_gemm(const float* __restrict__ xext, int asel, int dsel,
       const float* __restrict__ B0, const float* __restrict__ B1,
       const float* __restrict__ bias, float* __restrict__ oext) {
    constexpr int BM   = 128;
    constexpr int LDAP = 136;        // 8 mod 32 -> conflict-free frag loads
    constexpr int LDBP = NOUT + 8;
    constexpr int NT   = NOUT / 8;
    __shared__ uint32_t Ahp[16][LDAP];
    __shared__ uint32_t Alp[16][LDAP];
    __shared__ uint32_t Bhp[16][LDBP];
    __shared__ uint32_t Blp[16][LDBP];

    const float* __restrict__ A1 = sel_buf(asel, xext);
    const float* __restrict__ A0 = SPLIT ? (const float*)g_agg : A1;
    float* __restrict__ out = (dsel == 0) ? oext : (dsel == 1 ? g_h0 : g_h1);

    const int t     = threadIdx.x;
    const int lane  = t & 31;
    const int wid   = t >> 5;
    const int g     = lane >> 2;
    const int tg    = lane & 3;
    const int mbase = blockIdx.x * BM;
    const int ma    = wid * 16 + g;

    float c[NT][4];
    #pragma unroll
    for (int nt = 0; nt < NT; nt++)
        #pragma unroll
        for (int i = 0; i < 4; i++) c[nt][i] = 0.f;

    #pragma unroll 1
    for (int kt = 0; kt < KTOT; kt += 32) {
        const bool second = SPLIT && (kt >= 64);
        const float* __restrict__ Asrc = second ? A1 : A0;
        const float* __restrict__ Bsrc = second ? B1 : B0;
        const int kb = second ? (kt - 64) : kt;

        // stage A: 128 rows x 16 k2; thread -> (row, k2); float2 global reads coalesced
        #pragma unroll
        for (int idx = t; idx < BM * 16; idx += 256) {
            int row = idx >> 4;
            int k2  = idx & 15;
            int grow = mbase + row;
            float2 v = make_float2(0.f, 0.f);
            if (grow < NN) v = *(const float2*)&Asrc[(size_t)grow * 64 + kb + 2 * k2];
            uint32_t hp, lp;
            split_pack2(v.x, v.y, hp, lp);
            Ahp[k2][row] = hp;
            Alp[k2][row] = lp;
        }
        // stage B: 16 k2 x NOUT
        #pragma unroll
        for (int idx = t; idx < 16 * NOUT; idx += 256) {
            int k2 = idx / NOUT;
            int cc = idx % NOUT;
            float w0 = Bsrc[(size_t)(kb + 2 * k2) * NOUT + cc];
            float w1 = Bsrc[(size_t)(kb + 2 * k2 + 1) * NOUT + cc];
            uint32_t hp, lp;
            split_pack2(w0, w1, hp, lp);
            Bhp[k2][cc] = hp;
            Blp[k2][cc] = lp;
        }
        __syncthreads();

        #pragma unroll
        for (int ks = 0; ks < 2; ks++) {
            const int kk = ks * 8 + tg;
            uint32_t ah[4], al[4];
            ah[0] = Ahp[kk][ma];      ah[1] = Ahp[kk][ma + 8];
            ah[2] = Ahp[kk + 4][ma];  ah[3] = Ahp[kk + 4][ma + 8];
            al[0] = Alp[kk][ma];      al[1] = Alp[kk][ma + 8];
            al[2] = Alp[kk + 4][ma];  al[3] = Alp[kk + 4][ma + 8];
            #pragma unroll
            for (int nt = 0; nt < NT; nt++) {
                const int col = nt * 8 + g;
                uint32_t bh0 = Bhp[kk][col];
                uint32_t bh1 = Bhp[kk + 4][col];
                uint32_t bl0 = Blp[kk][col];
                uint32_t bl1 = Blp[kk + 4][col];
                mma_bf16(c[nt], al, bh0, bh1);   // small terms first
                mma_bf16(c[nt], ah, bl0, bl1);
                mma_bf16(c[nt], ah, bh0, bh1);
            }
        }
        __syncthreads();
    }

    // epilogue: bias (+ReLU), float2 stores
    const int r0 = mbase + wid * 16 + g;
    const int r1 = r0 + 8;
    #pragma unroll
    for (int nt = 0; nt < NT; nt++) {
        const int col = nt * 8 + 2 * tg;
        float bx = bias[col];
        float by = bias[col + 1];
        if (r0 < NN) {
            float vx = c[nt][0] + bx;
            float vy = c[nt][1] + by;
            if (RELU) { vx = fmaxf(vx, 0.f); vy = fmaxf(vy, 0.f); }
            *(float2*)&out[(size_t)r0 * NOUT + col] = make_float2(vx, vy);
        }
        if (r1 < NN) {
            float vx = c[nt][2] + bx;
            float vy = c[nt][3] + by;
            if (RELU) { vx = fmaxf(vx, 0.f); vy = fmaxf(vy, 0.f); }
            *(float2*)&out[(size_t)r1 * NOUT + col] = make_float2(vx, vy);
        }
    }
}

// ---------------- host launcher (pure kernel launches; graph-capturable) ----------------
extern "C" void kernel_launch(void* const* d_in, const int* in_sizes, int n_in,
                              void* d_out, int out_size) {
    const float* x    = (const float*)d_in[0];
    const int*   ei   = (const int*)d_in[1];
    const float* Wl1  = (const float*)d_in[2];
    const float* Wr1  = (const float*)d_in[3];
    const float* b1   = (const float*)d_in[4];
    const float* Wl2  = (const float*)d_in[5];
    const float* Wr2  = (const float*)d_in[6];
    const float* b2   = (const float*)d_in[7];
    const float* Wl3  = (const float*)d_in[8];
    const float* Wr3  = (const float*)d_in[9];
    const float* b3   = (const float*)d_in[10];
    const float* Wlin = (const float*)d_in[11];
    const float* blin = (const float*)d_in[12];
    float*       out  = (float*)d_out;

    // CSR build
    k_zero_deg<<<CDIV(NN, 256), 256>>>();
    k_count<<<CDIV(NE, 256), 256>>>(ei);
    k_blocksum<<<NPART, SCAN_BS>>>();
    k_scanpart<<<1, 256>>>();
    k_offsets<<<NPART, SCAN_BS>>>();
    k_scatter<<<CDIV(NE, 256), 256>>>(ei);

    const int AGG_BLOCKS  = CDIV(NN, 8);
    const int GEMM_BLOCKS = CDIV(NN, 128);

    // layer 1
    k_agg<<<AGG_BLOCKS, 256>>>(x, 0);
    k_gemm<128, 64, true, true><<<GEMM_BLOCKS, 256>>>(x, 0, 1, Wl1, Wr1, b1, nullptr);
    // layer 2
    k_agg<<<AGG_BLOCKS, 256>>>(nullptr, 1);
    k_gemm<128, 64, true, true><<<GEMM_BLOCKS, 256>>>(nullptr, 1, 2, Wl2, Wr2, b2, nullptr);
    // layer 3
    k_agg<<<AGG_BLOCKS, 256>>>(nullptr, 2);
    k_gemm<128, 64, true, true><<<GEMM_BLOCKS, 256>>>(nullptr, 2, 1, Wl3, Wr3, b3, nullptr);
    // final linear
    k_gemm<64, 32, false, false><<<GEMM_BLOCKS, 256>>>(nullptr, 1, 0, Wlin, nullptr, blin, out);
}